// round 2
// baseline (speedup 1.0000x reference)
#include <cuda_runtime.h>
#include <math.h>

#define BB   8
#define HH   64
#define WW   64
#define DIM  768
#define MID  96
#define HWSZ 4096
#define KKB  4
#define KSZ  7

// ---------------- scratch (device globals; no allocation) ----------------
__device__ float g_xemb[BB * MID * HWSZ];     // [B, MID, H, W]
__device__ float g_temb[BB * MID * HWSZ];
__device__ float g_common[BB * MID * HWSZ];
__device__ float g_fds[BB * MID * HWSZ];
__device__ float g_gvec[BB * MID];
__device__ float g_dyn[BB * MID * KSZ * KSZ];
__device__ float g_upwT[MID * DIM];           // up_w transposed: [c][n]

// ---------------------------------------------------------------------------
// Kernel 1: fused LayerNorm + Linear(768->96), output NCHW.
// Tile: 32 pixels x 96 outputs, K-tiles of 64. 256 threads, TM=4, TN=3.
// ---------------------------------------------------------------------------
__global__ void ln_down_kernel(const float* __restrict__ x,
                               const float* __restrict__ lnw,
                               const float* __restrict__ lnb,
                               const float* __restrict__ w,
                               const float* __restrict__ wb,
                               int which)   // 0 -> g_xemb, 1 -> g_temb
{
    __shared__ float a_s[32 * 65];
    __shared__ float b_s[64 * 97];
    __shared__ float c_s[32 * 97];
    __shared__ float s_mean[32];
    __shared__ float s_rstd[32];

    const int tid  = threadIdx.x;
    const int m0   = blockIdx.x * 32;      // global pixel base
    const int warp = tid >> 5, lane = tid & 31;

    // ---- LN stats: 8 warps, 4 pixels each ----
    for (int p = warp * 4; p < warp * 4 + 4; p++) {
        const float* row = x + (size_t)(m0 + p) * DIM;
        float s = 0.f, s2 = 0.f;
        for (int i = lane; i < DIM; i += 32) {
            float v = row[i];
            s += v; s2 += v * v;
        }
        #pragma unroll
        for (int o = 16; o; o >>= 1) {
            s  += __shfl_xor_sync(0xffffffffu, s,  o);
            s2 += __shfl_xor_sync(0xffffffffu, s2, o);
        }
        if (lane == 0) {
            float mu  = s * (1.f / DIM);
            float var = s2 * (1.f / DIM) - mu * mu;
            s_mean[p] = mu;
            s_rstd[p] = rsqrtf(var + 1e-6f);
        }
    }
    __syncthreads();

    const int tn = tid & 31;   // n base = 3*tn
    const int tm = tid >> 5;   // m base = 4*tm
    float acc[4][3];
    #pragma unroll
    for (int i = 0; i < 4; i++)
        #pragma unroll
        for (int j = 0; j < 3; j++) acc[i][j] = 0.f;

    for (int kt = 0; kt < DIM; kt += 64) {
        // A tile: 32 x 64, LN applied on the fly. Coalesced loads, stride-1 stores.
        #pragma unroll
        for (int i = 0; i < 8; i++) {
            int e = tid + i * 256;
            int m = e >> 6, k = e & 63;
            float v = x[(size_t)(m0 + m) * DIM + kt + k];
            v = (v - s_mean[m]) * s_rstd[m] * lnw[kt + k] + lnb[kt + k];
            a_s[m * 65 + k] = v;
        }
        // B tile: 96 x 64 -> b_s[k][n] (pitch 97: conflict-free stores & loads)
        #pragma unroll
        for (int i = 0; i < 24; i++) {
            int e = tid + i * 256;
            int n = e >> 6, k = e & 63;
            b_s[k * 97 + n] = w[(size_t)n * DIM + kt + k];
        }
        __syncthreads();

        #pragma unroll 8
        for (int k = 0; k < 64; k++) {
            float a0 = a_s[(tm * 4 + 0) * 65 + k];
            float a1 = a_s[(tm * 4 + 1) * 65 + k];
            float a2 = a_s[(tm * 4 + 2) * 65 + k];
            float a3 = a_s[(tm * 4 + 3) * 65 + k];
            float b0 = b_s[k * 97 + tn * 3 + 0];
            float b1 = b_s[k * 97 + tn * 3 + 1];
            float b2 = b_s[k * 97 + tn * 3 + 2];
            acc[0][0] += a0 * b0; acc[0][1] += a0 * b1; acc[0][2] += a0 * b2;
            acc[1][0] += a1 * b0; acc[1][1] += a1 * b1; acc[1][2] += a1 * b2;
            acc[2][0] += a2 * b0; acc[2][1] += a2 * b1; acc[2][2] += a2 * b2;
            acc[3][0] += a3 * b0; acc[3][1] += a3 * b1; acc[3][2] += a3 * b2;
        }
        __syncthreads();
    }

    // stage results, then coalesced NCHW scatter
    #pragma unroll
    for (int i = 0; i < 4; i++)
        #pragma unroll
        for (int j = 0; j < 3; j++)
            c_s[(tm * 4 + i) * 97 + tn * 3 + j] = acc[i][j] + wb[tn * 3 + j];
    __syncthreads();

    float* out = which ? g_temb : g_xemb;
    const int b   = m0 >> 12;
    const int hw0 = m0 & 4095;
    #pragma unroll
    for (int i = 0; i < 12; i++) {
        int e = tid + i * 256;
        int n = e >> 5, m = e & 31;
        out[((size_t)b * MID + n) * HWSZ + hw0 + m] = c_s[m * 97 + n];
    }
}

// ---------------------------------------------------------------------------
// Kernel 2: gvec = mean over H*W of g_xemb plane. grid = B*MID.
// ---------------------------------------------------------------------------
__global__ void gvec_kernel()
{
    __shared__ float red[256];
    const int bc = blockIdx.x;
    const float* p = g_xemb + (size_t)bc * HWSZ;
    float s = 0.f;
    for (int i = threadIdx.x; i < HWSZ; i += 256) s += p[i];
    red[threadIdx.x] = s;
    __syncthreads();
    for (int o = 128; o; o >>= 1) {
        if (threadIdx.x < o) red[threadIdx.x] += red[threadIdx.x + o];
        __syncthreads();
    }
    if (threadIdx.x == 0) g_gvec[bc] = red[0] * (1.f / HWSZ);
}

// ---------------------------------------------------------------------------
// Kernel 3: per-batch MLP + softmax + dynamic kernel synthesis. grid = B.
// ---------------------------------------------------------------------------
__global__ void mlp_dyn_kernel(const float* __restrict__ m1w,
                               const float* __restrict__ m1b,
                               const float* __restrict__ m2w,
                               const float* __restrict__ m2b,
                               const float* __restrict__ basis)
{
    __shared__ float gv[MID];
    __shared__ float hid[24];
    __shared__ float wk[4];
    const int b = blockIdx.x, tid = threadIdx.x;

    if (tid < MID) gv[tid] = g_gvec[b * MID + tid];
    __syncthreads();

    if (tid < 24) {
        float s = m1b[tid];
        for (int c = 0; c < MID; c++) s += gv[c] * m1w[tid * MID + c];
        hid[tid] = fmaxf(s, 0.f);
    }
    __syncthreads();

    if (tid == 0) {
        float l[4];
        for (int k = 0; k < 4; k++) {
            float s = m2b[k];
            for (int j = 0; j < 24; j++) s += hid[j] * m2w[k * 24 + j];
            l[k] = s;
        }
        float mx = fmaxf(fmaxf(l[0], l[1]), fmaxf(l[2], l[3]));
        float e0 = expf(l[0] - mx), e1 = expf(l[1] - mx);
        float e2 = expf(l[2] - mx), e3 = expf(l[3] - mx);
        float inv = 1.f / (e0 + e1 + e2 + e3);
        wk[0] = e0 * inv; wk[1] = e1 * inv; wk[2] = e2 * inv; wk[3] = e3 * inv;
    }
    __syncthreads();

    const int n = MID * KSZ * KSZ;   // 4704
    for (int e = tid; e < n; e += 128) {
        float s = 0.f;
        #pragma unroll
        for (int k = 0; k < 4; k++) s += wk[k] * basis[k * n + e];
        g_dyn[b * n + e] = s;
    }
}

// ---------------------------------------------------------------------------
// Kernel 4: depthwise 3x3 + SiLU + 1x1 (96 -> 192) -> gamma/beta -> common.
// One block per (b, h) row. grid = B*H = 512, 256 threads.
// ---------------------------------------------------------------------------
__global__ void head_common_kernel(const float* __restrict__ dww,
                                   const float* __restrict__ dwb,
                                   const float* __restrict__ pww,
                                   const float* __restrict__ pwb)
{
    __shared__ float y_s[MID * WW];   // 96 x 64 (24.6 KB)
    const int b = blockIdx.x >> 6;
    const int h = blockIdx.x & 63;
    const float* tp = g_temb + (size_t)b * MID * HWSZ;

    for (int e = threadIdx.x; e < MID * WW; e += 256) {
        int c = e >> 6, wc = e & 63;
        const float* kw = dww + c * 9;
        float acc = 0.f;
        #pragma unroll
        for (int di = 0; di < 3; di++) {
            int hh = h + di - 1;
            if ((unsigned)hh < 64u) {
                const float* rowp = tp + (size_t)c * HWSZ + hh * 64;
                #pragma unroll
                for (int dj = 0; dj < 3; dj++) {
                    int wp = wc + dj - 1;
                    if ((unsigned)wp < 64u) acc += rowp[wp] * kw[di * 3 + dj];
                }
            }
        }
        float z = acc + dwb[c];
        y_s[c * 64 + wc] = z * (1.f / (1.f + expf(-z)));  // SiLU
    }
    __syncthreads();

    const float* xp = g_xemb + (size_t)b * MID * HWSZ + h * 64;
    float* cp = g_common + (size_t)b * MID * HWSZ + h * 64;
    for (int e = threadIdx.x; e < MID * WW; e += 256) {
        int c = e >> 6, wc = e & 63;
        float ga = pwb[c];
        float be = pwb[MID + c];
        const float* wg  = pww + (size_t)c * MID;
        const float* wbt = pww + (size_t)(MID + c) * MID;
        for (int cc = 0; cc < MID; cc++) {
            float yv = y_s[cc * 64 + wc];
            ga += yv * wg[cc];
            be += yv * wbt[cc];
        }
        float xe = xp[(size_t)c * HWSZ + wc];
        cp[(size_t)c * HWSZ + wc] = xe * (1.f + ga) + be;
    }
}

// ---------------------------------------------------------------------------
// Kernel 5: FDS as a direct circular 7x7 correlation (replaces rfft2/irfft2).
// out[y,x] = sum_{i,j} dyn[i,j] * common[(y+3-i)&63, (x+3-j)&63]
// One block per (b,c) plane. grid = 768.
// ---------------------------------------------------------------------------
__global__ void fds_kernel()
{
    __shared__ float pl[HWSZ];   // 16 KB plane
    __shared__ float dd[KSZ * KSZ];
    const int bc = blockIdx.x;
    const float* src = g_common + (size_t)bc * HWSZ;
    for (int i = threadIdx.x; i < HWSZ; i += 256) pl[i] = src[i];
    if (threadIdx.x < KSZ * KSZ) dd[threadIdx.x] = g_dyn[bc * KSZ * KSZ + threadIdx.x];
    __syncthreads();

    float* dst = g_fds + (size_t)bc * HWSZ;
    for (int p = threadIdx.x; p < HWSZ; p += 256) {
        int yy = p >> 6, xx = p & 63;
        float acc = 0.f;
        #pragma unroll
        for (int i = 0; i < KSZ; i++) {
            const float* rowp = pl + (((yy + 3 - i) & 63) << 6);
            #pragma unroll
            for (int j = 0; j < KSZ; j++) {
                acc += dd[i * KSZ + j] * rowp[(xx + 3 - j) & 63];
            }
        }
        dst[p] = acc;
    }
}

// ---------------------------------------------------------------------------
// Kernel 7 (prep): transpose up_w [768,96] -> g_upwT [96,768]
// ---------------------------------------------------------------------------
__global__ void transpose_upw(const float* __restrict__ w)
{
    int e = blockIdx.x * 256 + threadIdx.x;
    if (e < MID * DIM) {
        int c = e / DIM, n = e - c * DIM;
        g_upwT[e] = w[(size_t)n * MID + c];
    }
}

// ---------------------------------------------------------------------------
// Kernel 6: Linear(96->768) + bias + residual. GEMM M=32768, N=768, K=96.
// Tile: 32 pixels x 128 n, K-tiles of 32. 256 threads, TM=4, TN=4.
// ---------------------------------------------------------------------------
__global__ void up_kernel(const float* __restrict__ x,
                          const float* __restrict__ upb,
                          float* __restrict__ out)
{
    __shared__ float v_s[32 * 97];     // fds vectors, [m][c] pitch 97
    __shared__ float w_s[32 * 132];    // weight tile [k][n] pitch 132 (16B aligned rows)

    const int m0  = blockIdx.x * 32;
    const int b   = m0 >> 12;
    const int hw0 = m0 & 4095;
    const float* fp = g_fds + (size_t)b * MID * HWSZ + hw0;

    #pragma unroll
    for (int i = 0; i < 12; i++) {
        int e = threadIdx.x + i * 256;
        int c = e >> 5, m = e & 31;
        v_s[m * 97 + c] = fp[(size_t)c * HWSZ + m];
    }

    const int tn = threadIdx.x & 31;   // n base = 4*tn within tile
    const int tm = threadIdx.x >> 5;   // m base = 4*tm

    for (int nt = 0; nt < DIM; nt += 128) {
        float acc[4][4] = {};
        for (int ktile = 0; ktile < MID; ktile += 32) {
            __syncthreads();
            #pragma unroll
            for (int i = 0; i < 16; i++) {
                int e = threadIdx.x + i * 256;
                int k = e >> 7, n = e & 127;
                w_s[k * 132 + n] = g_upwT[(size_t)(ktile + k) * DIM + nt + n];
            }
            __syncthreads();
            #pragma unroll 8
            for (int k = 0; k < 32; k++) {
                float a0 = v_s[(tm * 4 + 0) * 97 + ktile + k];
                float a1 = v_s[(tm * 4 + 1) * 97 + ktile + k];
                float a2 = v_s[(tm * 4 + 2) * 97 + ktile + k];
                float a3 = v_s[(tm * 4 + 3) * 97 + ktile + k];
                float4 bv = *(const float4*)&w_s[k * 132 + tn * 4];
                acc[0][0] += a0 * bv.x; acc[0][1] += a0 * bv.y; acc[0][2] += a0 * bv.z; acc[0][3] += a0 * bv.w;
                acc[1][0] += a1 * bv.x; acc[1][1] += a1 * bv.y; acc[1][2] += a1 * bv.z; acc[1][3] += a1 * bv.w;
                acc[2][0] += a2 * bv.x; acc[2][1] += a2 * bv.y; acc[2][2] += a2 * bv.z; acc[2][3] += a2 * bv.w;
                acc[3][0] += a3 * bv.x; acc[3][1] += a3 * bv.y; acc[3][2] += a3 * bv.z; acc[3][3] += a3 * bv.w;
            }
        }
        // epilogue: + bias + residual, 16B vectorized
        const int nb = nt + tn * 4;
        float4 bias = *(const float4*)&upb[nb];
        #pragma unroll
        for (int mm = 0; mm < 4; mm++) {
            int m = tm * 4 + mm;
            size_t base = (size_t)(m0 + m) * DIM + nb;
            float4 xr = *(const float4*)&x[base];
            float4 o;
            o.x = acc[mm][0] + bias.x + xr.x;
            o.y = acc[mm][1] + bias.y + xr.y;
            o.z = acc[mm][2] + bias.z + xr.z;
            o.w = acc[mm][3] + bias.w + xr.w;
            *(float4*)&out[base] = o;
        }
        __syncthreads();  // protect w_s before next nt's first load
    }
}

// ---------------------------------------------------------------------------
extern "C" void kernel_launch(void* const* d_in, const int* in_sizes, int n_in,
                              void* d_out, int out_size)
{
    const float* x      = (const float*)d_in[0];
    const float* t      = (const float*)d_in[1];
    const float* ln_w   = (const float*)d_in[2];
    const float* ln_b   = (const float*)d_in[3];
    const float* down_w = (const float*)d_in[4];
    const float* down_b = (const float*)d_in[5];
    const float* ln1_w  = (const float*)d_in[6];
    const float* ln1_b  = (const float*)d_in[7];
    const float* down1_w= (const float*)d_in[8];
    const float* down1_b= (const float*)d_in[9];
    const float* dw_w   = (const float*)d_in[10];
    const float* dw_b   = (const float*)d_in[11];
    const float* pw_w   = (const float*)d_in[12];
    const float* pw_b   = (const float*)d_in[13];
    const float* mlp1_w = (const float*)d_in[14];
    const float* mlp1_b = (const float*)d_in[15];
    const float* mlp2_w = (const float*)d_in[16];
    const float* mlp2_b = (const float*)d_in[17];
    const float* basis  = (const float*)d_in[18];
    const float* up_w   = (const float*)d_in[19];
    const float* up_b   = (const float*)d_in[20];
    float* out = (float*)d_out;

    const int M_TILES = (BB * HWSZ) / 32;   // 1024

    ln_down_kernel<<<M_TILES, 256>>>(x, ln_w,  ln_b,  down_w,  down_b,  0);
    ln_down_kernel<<<M_TILES, 256>>>(t, ln1_w, ln1_b, down1_w, down1_b, 1);
    transpose_upw<<<(MID * DIM + 255) / 256, 256>>>(up_w);
    gvec_kernel<<<BB * MID, 256>>>();
    mlp_dyn_kernel<<<BB, 128>>>(mlp1_w, mlp1_b, mlp2_w, mlp2_b, basis);
    head_common_kernel<<<BB * HH, 256>>>(dw_w, dw_b, pw_w, pw_b);
    fds_kernel<<<BB * MID, 256>>>();
    up_kernel<<<M_TILES, 256>>>(x, up_b, out);
}

// round 7
// speedup vs baseline: 1.3661x; 1.3661x over previous
#include <cuda_runtime.h>
#include <cuda_bf16.h>
#include <cstdint>
#include <math.h>

#define BB   8
#define HH   64
#define WW   64
#define DIM  768
#define MID  96
#define HWSZ 4096
#define KSZ  7

// ====================== warp-MMA helpers (sm_80+ portable) ==================
__device__ __forceinline__ uint32_t smem_to_u32(const void* p) {
    uint32_t a;
    asm("{ .reg .u64 t; cvta.to.shared.u64 t, %1; cvt.u32.u64 %0, t; }"
        : "=r"(a) : "l"(p));
    return a;
}
__device__ __forceinline__ void ldsm_x4(unsigned* r, uint32_t addr) {
    asm volatile("ldmatrix.sync.aligned.m8n8.x4.shared.b16 {%0,%1,%2,%3}, [%4];"
        : "=r"(r[0]), "=r"(r[1]), "=r"(r[2]), "=r"(r[3]) : "r"(addr));
}
__device__ __forceinline__ void ldsm_x2(unsigned* r, uint32_t addr) {
    asm volatile("ldmatrix.sync.aligned.m8n8.x2.shared.b16 {%0,%1}, [%2];"
        : "=r"(r[0]), "=r"(r[1]) : "r"(addr));
}
__device__ __forceinline__ void mma16816(float* c, const unsigned* a, const unsigned* b) {
    asm volatile("mma.sync.aligned.m16n8k16.row.col.f32.bf16.bf16.f32 "
        "{%0,%1,%2,%3}, {%4,%5,%6,%7}, {%8,%9}, {%0,%1,%2,%3};"
        : "+f"(c[0]), "+f"(c[1]), "+f"(c[2]), "+f"(c[3])
        : "r"(a[0]), "r"(a[1]), "r"(a[2]), "r"(a[3]), "r"(b[0]), "r"(b[1]));
}

// split fp32 pair -> bf16x2 hi word (ret) + bf16x2 lo word (out-param)
__device__ __forceinline__ unsigned pack_split(float y0, float y1, unsigned& lo_out) {
    __nv_bfloat16 h0 = __float2bfloat16_rn(y0);
    __nv_bfloat16 h1 = __float2bfloat16_rn(y1);
    float r0 = y0 - __bfloat162float(h0);
    float r1 = y1 - __bfloat162float(h1);
    __nv_bfloat16 l0 = __float2bfloat16_rn(r0);
    __nv_bfloat16 l1 = __float2bfloat16_rn(r1);
    lo_out = (unsigned)__bfloat16_as_ushort(l0) | ((unsigned)__bfloat16_as_ushort(l1) << 16);
    return (unsigned)__bfloat16_as_ushort(h0) | ((unsigned)__bfloat16_as_ushort(h1) << 16);
}

// ============================ scratch =======================================
__device__ float g_xemb[BB * MID * HWSZ];
__device__ float g_temb[BB * MID * HWSZ];
__device__ float g_common[BB * MID * HWSZ];
__device__ float g_fds[BB * MID * HWSZ];
__device__ float g_gvec[BB * MID];
__device__ float g_dyn[BB * MID * KSZ * KSZ];
__device__ float g_mu[2 * BB * HWSZ];
__device__ float g_rs[2 * BB * HWSZ];
// pre-split weights, plain [n][k] bf16 rows (as u32 bf16x2 words)
__device__ __align__(16) unsigned g_bdn_hi[2 * 96 * 384];   // [which][n=96][k2=384]
__device__ __align__(16) unsigned g_bdn_lo[2 * 96 * 384];
__device__ __align__(16) unsigned g_bup_hi[768 * 48];       // [n=768][k2=48]
__device__ __align__(16) unsigned g_bup_lo[768 * 48];

// ---------------------------------------------------------------------------
// LN stats pre-pass: one warp per pixel, both inputs in one launch.
// ---------------------------------------------------------------------------
__global__ void stats_kernel(const float* __restrict__ x, const float* __restrict__ t)
{
    const int wid = threadIdx.x >> 5, lane = threadIdx.x & 31;
    const int pix = blockIdx.x * 8 + wid;                 // 0 .. 65535
    const float* src = (pix >= BB * HWSZ) ? t : x;
    const int p = pix & (BB * HWSZ - 1);
    const float4* row = (const float4*)(src + (size_t)p * DIM);
    float s = 0.f, s2 = 0.f;
    #pragma unroll
    for (int j = 0; j < 6; j++) {
        float4 v = row[lane + 32 * j];
        s  += v.x + v.y + v.z + v.w;
        s2 += v.x * v.x + v.y * v.y + v.z * v.z + v.w * v.w;
    }
    #pragma unroll
    for (int o = 16; o; o >>= 1) {
        s  += __shfl_xor_sync(0xffffffffu, s,  o);
        s2 += __shfl_xor_sync(0xffffffffu, s2, o);
    }
    if (lane == 0) {
        float mu  = s * (1.f / DIM);
        float var = s2 * (1.f / DIM) - mu * mu;
        g_mu[pix] = mu;
        g_rs[pix] = rsqrtf(var + 1e-6f);
    }
}

// ---------------------------------------------------------------------------
// Weight prep: split fp32 -> bf16 hi/lo words, plain [n][k2] layout.
// ---------------------------------------------------------------------------
__global__ void prep_down_kernel(const float* __restrict__ w0, const float* __restrict__ w1)
{
    int e = blockIdx.x * 256 + threadIdx.x;               // < 73728
    if (e >= 2 * 96 * 384) return;
    int k2 = e % 384;
    int tmp = e / 384;
    int r = tmp % 96;
    int which = tmp / 96;
    const float* w = which ? w1 : w0;
    float v0 = w[(size_t)r * DIM + 2 * k2];
    float v1 = w[(size_t)r * DIM + 2 * k2 + 1];
    unsigned lo, hi = pack_split(v0, v1, lo);
    g_bdn_hi[e] = hi;
    g_bdn_lo[e] = lo;
}

__global__ void prep_up_kernel(const float* __restrict__ upw)
{
    int e = blockIdx.x * 256 + threadIdx.x;               // < 36864
    if (e >= 768 * 48) return;
    int k2 = e % 48;
    int n  = e / 48;
    float v0 = upw[(size_t)n * MID + 2 * k2];
    float v1 = upw[(size_t)n * MID + 2 * k2 + 1];
    unsigned lo, hi = pack_split(v0, v1, lo);
    g_bup_hi[e] = hi;
    g_bup_lo[e] = lo;
}

// ---------------------------------------------------------------------------
// Fused LN + Linear(768->96) via mma.sync split-bf16. 128 pixels/CTA, N=96.
// smem (dynamic, 64 KB):
//   [0 mu 512][512 rs 512][1024 A_hi 18432][19456 A_lo 18432]
//   [37888 B_hi 13824][51712 B_lo 13824]   (pitch 72 bf16 = 144 B rows)
// ---------------------------------------------------------------------------
#define LN_SMEM 65536
#define LN_AHI  1024
#define LN_ALO  19456
#define LN_BHI  37888
#define LN_BLO  51712
__global__ void ln_down_mma_kernel(const float* __restrict__ x,
                                   const float* __restrict__ lnw,
                                   const float* __restrict__ lnb,
                                   const float* __restrict__ wb,
                                   int which)
{
    extern __shared__ __align__(16) char smem[];
    const uint32_t sb = smem_to_u32(smem);
    const int tid = threadIdx.x, wid = tid >> 5, lane = tid & 31;

    const int m0 = blockIdx.x * 128;
    const int b = m0 >> 12, hw0 = m0 & 4095;
    const int base_pix = which * (BB * HWSZ) + m0;
    float* s_mu = (float*)(smem);
    float* s_rs = (float*)(smem + 512);
    if (tid < 128) {
        s_mu[tid] = g_mu[base_pix + tid];
        s_rs[tid] = g_rs[base_pix + tid];
    }

    unsigned* aH = (unsigned*)(smem + LN_AHI);
    unsigned* aL = (unsigned*)(smem + LN_ALO);
    unsigned* bH = (unsigned*)(smem + LN_BHI);
    unsigned* bL = (unsigned*)(smem + LN_BLO);

    float acc[12][4];
    #pragma unroll
    for (int i = 0; i < 12; i++)
        #pragma unroll
        for (int j = 0; j < 4; j++) acc[i][j] = 0.f;

    const int m0w = (wid * 16);

    for (int kt = 0; kt < 12; kt++) {
        __syncthreads();   // previous iteration's ldmatrix reads complete
        // A tile: 128 x 64, LN applied, split hi/lo. word idx = m*36 + c2
        #pragma unroll
        for (int i = 0; i < 16; i++) {
            int e = tid + i * 256;
            int m = e >> 5, c2 = e & 31, c = c2 * 2;
            float2 v  = *(const float2*)(x + (size_t)(m0 + m) * DIM + kt * 64 + c);
            float2 wv = *(const float2*)(lnw + kt * 64 + c);
            float2 bv = *(const float2*)(lnb + kt * 64 + c);
            float mu = s_mu[m], rs = s_rs[m];
            float y0 = (v.x - mu) * rs * wv.x + bv.x;
            float y1 = (v.y - mu) * rs * wv.y + bv.y;
            unsigned lo, hi = pack_split(y0, y1, lo);
            aH[m * 36 + c2] = hi;
            aL[m * 36 + c2] = lo;
        }
        // B tile: 96 rows x 32 words from pre-split weights
        #pragma unroll
        for (int i = 0; i < 12; i++) {
            int e = tid + i * 256;
            int n = e >> 5, k2 = e & 31;
            int src = which * 36864 + n * 384 + kt * 32 + k2;
            bH[n * 36 + k2] = g_bdn_hi[src];
            bL[n * 36 + k2] = g_bdn_lo[src];
        }
        __syncthreads();

        #pragma unroll
        for (int k16 = 0; k16 < 4; k16++) {
            unsigned ah[4], al[4];
            uint32_t arow = (uint32_t)((m0w + (lane & 15)) * 144 + k16 * 32 + (lane >> 4) * 16);
            ldsm_x4(ah, sb + LN_AHI + arow);
            ldsm_x4(al, sb + LN_ALO + arow);
            #pragma unroll
            for (int nt8 = 0; nt8 < 12; nt8++) {
                unsigned bh[2], bl[2];
                uint32_t brow = (uint32_t)((nt8 * 8 + (lane & 7)) * 144 + k16 * 32 + ((lane >> 3) & 1) * 16);
                ldsm_x2(bh, sb + LN_BHI + brow);
                ldsm_x2(bl, sb + LN_BLO + brow);
                mma16816(acc[nt8], ah, bh);
                mma16816(acc[nt8], ah, bl);
                mma16816(acc[nt8], al, bh);
            }
        }
    }

    // epilogue: direct NCHW stores (+ bias). D frag: c0=(m,n) c1=(m,n+1) c2=(m+8,n) c3=(m+8,n+1)
    float* outp = which ? g_temb : g_xemb;
    const int mlo = m0w + (lane >> 2);
    #pragma unroll
    for (int nt8 = 0; nt8 < 12; nt8++) {
        int n = nt8 * 8 + (lane & 3) * 2;
        float b0 = wb[n], b1 = wb[n + 1];
        size_t p0 = ((size_t)(b * MID + n)) * HWSZ + hw0;
        size_t p1 = ((size_t)(b * MID + n + 1)) * HWSZ + hw0;
        outp[p0 + mlo]     = acc[nt8][0] + b0;
        outp[p1 + mlo]     = acc[nt8][1] + b1;
        outp[p0 + mlo + 8] = acc[nt8][2] + b0;
        outp[p1 + mlo + 8] = acc[nt8][3] + b1;
    }
}

// ---------------------------------------------------------------------------
// up: Linear(96->768) + bias + residual via mma.sync split-bf16.
// 128 pixels/CTA, 6 N-tiles of 128, K=96 (6 k16 steps).
// smem (dynamic, 104 KB): pitch 104 bf16 = 208 B rows
//   [0 A_hi 26624][26624 A_lo 26624][53248 B_hi 26624][79872 B_lo 26624]
// ---------------------------------------------------------------------------
#define UP_SMEM 106496
#define UP_AHI  0
#define UP_ALO  26624
#define UP_BHI  53248
#define UP_BLO  79872
__global__ void up_mma_kernel(const float* __restrict__ x,
                              const float* __restrict__ upb,
                              float* __restrict__ out)
{
    extern __shared__ __align__(16) char smem[];
    const uint32_t sb = smem_to_u32(smem);
    const int tid = threadIdx.x, wid = tid >> 5, lane = tid & 31;

    const int m0 = blockIdx.x * 128;
    const int b = m0 >> 12, hw0 = m0 & 4095;
    const float* fp = g_fds + (size_t)b * MID * HWSZ + hw0;

    unsigned* aH = (unsigned*)(smem + UP_AHI);
    unsigned* aL = (unsigned*)(smem + UP_ALO);
    unsigned* bH = (unsigned*)(smem + UP_BHI);
    unsigned* bL = (unsigned*)(smem + UP_BLO);

    // A: 128 pixels x 96 channels (transpose from NCHW), split bf16. word = m*52 + c2
    #pragma unroll
    for (int i = 0; i < 24; i++) {
        int e = tid + i * 256;
        int m = e & 127, c2 = e >> 7, c = c2 * 2;      // c2 in 0..47
        float v0 = fp[(size_t)c * HWSZ + m];
        float v1 = fp[(size_t)(c + 1) * HWSZ + m];
        unsigned lo, hi = pack_split(v0, v1, lo);
        aH[m * 52 + c2] = hi;
        aL[m * 52 + c2] = lo;
    }

    const int m0w = wid * 16;
    const int mlo = m0w + (lane >> 2);

    for (int nt = 0; nt < 6; nt++) {
        __syncthreads();   // previous nt's ldmatrix reads complete
        // B tile: 128 rows (n = nt*128 + nl) x 48 words
        #pragma unroll
        for (int i = 0; i < 24; i++) {
            int e = tid + i * 256;
            int nl = e / 48, k2 = e - nl * 48;
            int src = (nt * 128 + nl) * 48 + k2;
            bH[nl * 52 + k2] = g_bup_hi[src];
            bL[nl * 52 + k2] = g_bup_lo[src];
        }
        __syncthreads();

        float acc[16][4];
        #pragma unroll
        for (int i = 0; i < 16; i++)
            #pragma unroll
            for (int j = 0; j < 4; j++) acc[i][j] = 0.f;

        #pragma unroll
        for (int k16 = 0; k16 < 6; k16++) {
            unsigned ah[4], al[4];
            uint32_t arow = (uint32_t)((m0w + (lane & 15)) * 208 + k16 * 32 + (lane >> 4) * 16);
            ldsm_x4(ah, sb + UP_AHI + arow);
            ldsm_x4(al, sb + UP_ALO + arow);
            #pragma unroll
            for (int nt8 = 0; nt8 < 16; nt8++) {
                unsigned bh[2], bl[2];
                uint32_t brow = (uint32_t)((nt8 * 8 + (lane & 7)) * 208 + k16 * 32 + ((lane >> 3) & 1) * 16);
                ldsm_x2(bh, sb + UP_BHI + brow);
                ldsm_x2(bl, sb + UP_BLO + brow);
                mma16816(acc[nt8], ah, bh);
                mma16816(acc[nt8], ah, bl);
                mma16816(acc[nt8], al, bh);
            }
        }

        // epilogue: bias + residual, float2 per lane per row
        #pragma unroll
        for (int nt8 = 0; nt8 < 16; nt8++) {
            int n = nt * 128 + nt8 * 8 + (lane & 3) * 2;
            float b0 = upb[n], b1 = upb[n + 1];
            size_t base0 = (size_t)(m0 + mlo) * DIM + n;
            size_t base1 = (size_t)(m0 + mlo + 8) * DIM + n;
            float2 x0 = *(const float2*)&x[base0];
            float2 x1 = *(const float2*)&x[base1];
            float2 o0, o1;
            o0.x = acc[nt8][0] + b0 + x0.x;
            o0.y = acc[nt8][1] + b1 + x0.y;
            o1.x = acc[nt8][2] + b0 + x1.x;
            o1.y = acc[nt8][3] + b1 + x1.y;
            *(float2*)&out[base0] = o0;
            *(float2*)&out[base1] = o1;
        }
    }
}

// ---------------------------------------------------------------------------
// gvec = mean over H*W of g_xemb plane. grid = B*MID.
// ---------------------------------------------------------------------------
__global__ void gvec_kernel()
{
    __shared__ float red[256];
    const int bc = blockIdx.x;
    const float* p = g_xemb + (size_t)bc * HWSZ;
    float s = 0.f;
    for (int i = threadIdx.x; i < HWSZ; i += 256) s += p[i];
    red[threadIdx.x] = s;
    __syncthreads();
    for (int o = 128; o; o >>= 1) {
        if (threadIdx.x < o) red[threadIdx.x] += red[threadIdx.x + o];
        __syncthreads();
    }
    if (threadIdx.x == 0) g_gvec[bc] = red[0] * (1.f / HWSZ);
}

// ---------------------------------------------------------------------------
// per-batch MLP + softmax + dynamic kernel synthesis. grid = B.
// ---------------------------------------------------------------------------
__global__ void mlp_dyn_kernel(const float* __restrict__ m1w,
                               const float* __restrict__ m1b,
                               const float* __restrict__ m2w,
                               const float* __restrict__ m2b,
                               const float* __restrict__ basis)
{
    __shared__ float gv[MID];
    __shared__ float hid[24];
    __shared__ float wk[4];
    const int b = blockIdx.x, tid = threadIdx.x;

    if (tid < MID) gv[tid] = g_gvec[b * MID + tid];
    __syncthreads();
    if (tid < 24) {
        float s = m1b[tid];
        for (int c = 0; c < MID; c++) s += gv[c] * m1w[tid * MID + c];
        hid[tid] = fmaxf(s, 0.f);
    }
    __syncthreads();
    if (tid == 0) {
        float l[4];
        for (int k = 0; k < 4; k++) {
            float s = m2b[k];
            for (int j = 0; j < 24; j++) s += hid[j] * m2w[k * 24 + j];
            l[k] = s;
        }
        float mx = fmaxf(fmaxf(l[0], l[1]), fmaxf(l[2], l[3]));
        float e0 = expf(l[0] - mx), e1 = expf(l[1] - mx);
        float e2 = expf(l[2] - mx), e3 = expf(l[3] - mx);
        float inv = 1.f / (e0 + e1 + e2 + e3);
        wk[0] = e0 * inv; wk[1] = e1 * inv; wk[2] = e2 * inv; wk[3] = e3 * inv;
    }
    __syncthreads();
    const int n = MID * KSZ * KSZ;
    for (int e = tid; e < n; e += 128) {
        float s = 0.f;
        #pragma unroll
        for (int k = 0; k < 4; k++) s += wk[k] * basis[k * n + e];
        g_dyn[b * n + e] = s;
    }
}

// ---------------------------------------------------------------------------
// depthwise 3x3 + SiLU + 1x1 (96->192) -> gamma/beta -> common.
// ---------------------------------------------------------------------------
__global__ void head_common_kernel(const float* __restrict__ dww,
                                   const float* __restrict__ dwb,
                                   const float* __restrict__ pww,
                                   const float* __restrict__ pwb)
{
    __shared__ float y_s[MID * WW];
    const int b = blockIdx.x >> 6;
    const int h = blockIdx.x & 63;
    const float* tp = g_temb + (size_t)b * MID * HWSZ;

    for (int e = threadIdx.x; e < MID * WW; e += 256) {
        int c = e >> 6, wc = e & 63;
        const float* kw = dww + c * 9;
        float acc = 0.f;
        #pragma unroll
        for (int di = 0; di < 3; di++) {
            int hh = h + di - 1;
            if ((unsigned)hh < 64u) {
                const float* rowp = tp + (size_t)c * HWSZ + hh * 64;
                #pragma unroll
                for (int dj = 0; dj < 3; dj++) {
                    int wp = wc + dj - 1;
                    if ((unsigned)wp < 64u) acc += rowp[wp] * kw[di * 3 + dj];
                }
            }
        }
        float z = acc + dwb[c];
        y_s[c * 64 + wc] = z * (1.f / (1.f + expf(-z)));
    }
    __syncthreads();

    const float* xp = g_xemb + (size_t)b * MID * HWSZ + h * 64;
    float* cp = g_common + (size_t)b * MID * HWSZ + h * 64;
    for (int e = threadIdx.x; e < MID * WW; e += 256) {
        int c = e >> 6, wc = e & 63;
        float ga = pwb[c];
        float be = pwb[MID + c];
        const float* wg  = pww + (size_t)c * MID;
        const float* wbt = pww + (size_t)(MID + c) * MID;
        for (int cc = 0; cc < MID; cc++) {
            float yv = y_s[cc * 64 + wc];
            ga += yv * wg[cc];
            be += yv * wbt[cc];
        }
        float xe = xp[(size_t)c * HWSZ + wc];
        cp[(size_t)c * HWSZ + wc] = xe * (1.f + ga) + be;
    }
}

// ---------------------------------------------------------------------------
// FDS: circular 7x7 correlation (== rfft2/irfft2 of padded+rolled kernel).
// ---------------------------------------------------------------------------
__global__ void fds_kernel()
{
    __shared__ float pl[HWSZ];
    __shared__ float dd[KSZ * KSZ];
    const int bc = blockIdx.x;
    const float* src = g_common + (size_t)bc * HWSZ;
    for (int i = threadIdx.x; i < HWSZ; i += 256) pl[i] = src[i];
    if (threadIdx.x < KSZ * KSZ) dd[threadIdx.x] = g_dyn[bc * KSZ * KSZ + threadIdx.x];
    __syncthreads();

    float* dst = g_fds + (size_t)bc * HWSZ;
    for (int p = threadIdx.x; p < HWSZ; p += 256) {
        int yy = p >> 6, xx = p & 63;
        float acc = 0.f;
        #pragma unroll
        for (int i = 0; i < KSZ; i++) {
            const float* rowp = pl + (((yy + 3 - i) & 63) << 6);
            #pragma unroll
            for (int j = 0; j < KSZ; j++)
                acc += dd[i * KSZ + j] * rowp[(xx + 3 - j) & 63];
        }
        dst[p] = acc;
    }
}

// ---------------------------------------------------------------------------
extern "C" void kernel_launch(void* const* d_in, const int* in_sizes, int n_in,
                              void* d_out, int out_size)
{
    const float* x      = (const float*)d_in[0];
    const float* t      = (const float*)d_in[1];
    const float* ln_w   = (const float*)d_in[2];
    const float* ln_b   = (const float*)d_in[3];
    const float* down_w = (const float*)d_in[4];
    const float* down_b = (const float*)d_in[5];
    const float* ln1_w  = (const float*)d_in[6];
    const float* ln1_b  = (const float*)d_in[7];
    const float* down1_w= (const float*)d_in[8];
    const float* down1_b= (const float*)d_in[9];
    const float* dw_w   = (const float*)d_in[10];
    const float* dw_b   = (const float*)d_in[11];
    const float* pw_w   = (const float*)d_in[12];
    const float* pw_b   = (const float*)d_in[13];
    const float* mlp1_w = (const float*)d_in[14];
    const float* mlp1_b = (const float*)d_in[15];
    const float* mlp2_w = (const float*)d_in[16];
    const float* mlp2_b = (const float*)d_in[17];
    const float* basis  = (const float*)d_in[18];
    const float* up_w   = (const float*)d_in[19];
    const float* up_b   = (const float*)d_in[20];
    float* out = (float*)d_out;

    cudaFuncSetAttribute(ln_down_mma_kernel,
                         cudaFuncAttributeMaxDynamicSharedMemorySize, LN_SMEM);
    cudaFuncSetAttribute(up_mma_kernel,
                         cudaFuncAttributeMaxDynamicSharedMemorySize, UP_SMEM);

    stats_kernel<<<8192, 256>>>(x, t);
    prep_down_kernel<<<288, 256>>>(down_w, down1_w);
    prep_up_kernel<<<144, 256>>>(up_w);
    ln_down_mma_kernel<<<256, 256, LN_SMEM>>>(x, ln_w,  ln_b,  down_b,  0);
    ln_down_mma_kernel<<<256, 256, LN_SMEM>>>(t, ln1_w, ln1_b, down1_b, 1);
    gvec_kernel<<<BB * MID, 256>>>();
    mlp_dyn_kernel<<<BB, 128>>>(mlp1_w, mlp1_b, mlp2_w, mlp2_b, basis);
    head_common_kernel<<<BB * HH, 256>>>(dw_w, dw_b, pw_w, pw_b);
    fds_kernel<<<BB * MID, 256>>>();
    up_mma_kernel<<<256, 256, UP_SMEM>>>(x, up_b, out);
}

// round 12
// speedup vs baseline: 1.7491x; 1.2804x over previous
#include <cuda_runtime.h>
#include <cuda_bf16.h>
#include <cstdint>
#include <math.h>

#define BB   8
#define HH   64
#define WW   64
#define DIM  768
#define MID  96
#define HWSZ 4096
#define KSZ  7

// ====================== warp-MMA helpers (sm_80+ portable) ==================
__device__ __forceinline__ uint32_t smem_to_u32(const void* p) {
    uint32_t a;
    asm("{ .reg .u64 t; cvta.to.shared.u64 t, %1; cvt.u32.u64 %0, t; }"
        : "=r"(a) : "l"(p));
    return a;
}
__device__ __forceinline__ void ldsm_x4(unsigned* r, uint32_t addr) {
    asm volatile("ldmatrix.sync.aligned.m8n8.x4.shared.b16 {%0,%1,%2,%3}, [%4];"
        : "=r"(r[0]), "=r"(r[1]), "=r"(r[2]), "=r"(r[3]) : "r"(addr));
}
__device__ __forceinline__ void mma16816(float* c, const unsigned* a, const unsigned* b) {
    asm volatile("mma.sync.aligned.m16n8k16.row.col.f32.bf16.bf16.f32 "
        "{%0,%1,%2,%3}, {%4,%5,%6,%7}, {%8,%9}, {%0,%1,%2,%3};"
        : "+f"(c[0]), "+f"(c[1]), "+f"(c[2]), "+f"(c[3])
        : "r"(a[0]), "r"(a[1]), "r"(a[2]), "r"(a[3]), "r"(b[0]), "r"(b[1]));
}

// split fp32 pair -> bf16x2 hi word (ret) + bf16x2 lo word (out-param)
__device__ __forceinline__ unsigned pack_split(float y0, float y1, unsigned& lo_out) {
    __nv_bfloat16 h0 = __float2bfloat16_rn(y0);
    __nv_bfloat16 h1 = __float2bfloat16_rn(y1);
    float r0 = y0 - __bfloat162float(h0);
    float r1 = y1 - __bfloat162float(h1);
    __nv_bfloat16 l0 = __float2bfloat16_rn(r0);
    __nv_bfloat16 l1 = __float2bfloat16_rn(r1);
    lo_out = (unsigned)__bfloat16_as_ushort(l0) | ((unsigned)__bfloat16_as_ushort(l1) << 16);
    return (unsigned)__bfloat16_as_ushort(h0) | ((unsigned)__bfloat16_as_ushort(h1) << 16);
}

// ============================ scratch =======================================
__device__ float g_xemb[BB * MID * HWSZ];
__device__ float g_temb[BB * MID * HWSZ];
__device__ float g_common[BB * MID * HWSZ];
__device__ float g_fds[BB * MID * HWSZ];
__device__ float g_gvec[BB * MID];
__device__ float g_dyn[BB * MID * KSZ * KSZ];
__device__ float g_mu[2 * BB * HWSZ];
__device__ float g_rs[2 * BB * HWSZ];
// pre-split weights in mma FRAGMENT order:
// down: [which][k16 0..47][nt8 0..11][lane 0..31][w 0..1]
__device__ __align__(16) unsigned g_bdn_hi[2 * 48 * 12 * 64];
__device__ __align__(16) unsigned g_bdn_lo[2 * 48 * 12 * 64];
// up: [k16 0..5][nt8 0..95][lane][w]
__device__ __align__(16) unsigned g_bup_hi[6 * 96 * 64];
__device__ __align__(16) unsigned g_bup_lo[6 * 96 * 64];

// ---------------------------------------------------------------------------
// LN stats pre-pass: one warp per pixel, both inputs in one launch.
// ---------------------------------------------------------------------------
__global__ void stats_kernel(const float* __restrict__ x, const float* __restrict__ t)
{
    const int wid = threadIdx.x >> 5, lane = threadIdx.x & 31;
    const int pix = blockIdx.x * 8 + wid;                 // 0 .. 65535
    const float* src = (pix >= BB * HWSZ) ? t : x;
    const int p = pix & (BB * HWSZ - 1);
    const float4* row = (const float4*)(src + (size_t)p * DIM);
    float s = 0.f, s2 = 0.f;
    #pragma unroll
    for (int j = 0; j < 6; j++) {
        float4 v = row[lane + 32 * j];
        s  += v.x + v.y + v.z + v.w;
        s2 += v.x * v.x + v.y * v.y + v.z * v.z + v.w * v.w;
    }
    #pragma unroll
    for (int o = 16; o; o >>= 1) {
        s  += __shfl_xor_sync(0xffffffffu, s,  o);
        s2 += __shfl_xor_sync(0xffffffffu, s2, o);
    }
    if (lane == 0) {
        float mu  = s * (1.f / DIM);
        float var = s2 * (1.f / DIM) - mu * mu;
        g_mu[pix] = mu;
        g_rs[pix] = rsqrtf(var + 1e-6f);
    }
}

// ---------------------------------------------------------------------------
// Weight prep -> fragment-order split-bf16 layouts.
// ---------------------------------------------------------------------------
__global__ void prep_down_kernel(const float* __restrict__ w0, const float* __restrict__ w1)
{
    int e = blockIdx.x * 256 + threadIdx.x;               // < 73728
    if (e >= 2 * 48 * 12 * 64) return;
    int w    = e & 1;
    int t    = e >> 1;
    int lane = t & 31;  t >>= 5;
    int nt8  = t % 12;  t /= 12;
    int k16  = t % 48;
    int which = t / 48;
    const float* wp = which ? w1 : w0;
    int n = nt8 * 8 + (lane >> 2);
    int k = k16 * 16 + (lane & 3) * 2 + w * 8;
    float v0 = wp[(size_t)n * DIM + k];
    float v1 = wp[(size_t)n * DIM + k + 1];
    unsigned lo, hi = pack_split(v0, v1, lo);
    g_bdn_hi[e] = hi;
    g_bdn_lo[e] = lo;
}

__global__ void prep_up_kernel(const float* __restrict__ upw)
{
    int e = blockIdx.x * 256 + threadIdx.x;               // < 36864
    if (e >= 6 * 96 * 64) return;
    int w    = e & 1;
    int t    = e >> 1;
    int lane = t & 31;  t >>= 5;
    int nt8  = t % 96;
    int k16  = t / 96;
    int n = nt8 * 8 + (lane >> 2);
    int k = k16 * 16 + (lane & 3) * 2 + w * 8;
    float v0 = upw[(size_t)n * MID + k];
    float v1 = upw[(size_t)n * MID + k + 1];
    unsigned lo, hi = pack_split(v0, v1, lo);
    g_bup_hi[e] = hi;
    g_bup_lo[e] = lo;
}

// ---------------------------------------------------------------------------
// Fused LN + Linear(768->96), register-resident mma.sync. No smem, no barriers.
// 128 pixels/CTA (8 warps x 16 rows), N=96, K=768 (48 k16 steps).
// ---------------------------------------------------------------------------
__global__ void __launch_bounds__(256, 2)
ln_down_mma_kernel(const float* __restrict__ x,
                   const float* __restrict__ lnw,
                   const float* __restrict__ lnb,
                   const float* __restrict__ wb,
                   int which)
{
    const int tid = threadIdx.x, wid = tid >> 5, lane = tid & 31;
    const int m0 = blockIdx.x * 128;
    const int b = m0 >> 12, hw0 = m0 & 4095;
    const int base_pix = which * (BB * HWSZ) + m0;

    const int r0 = wid * 16 + (lane >> 2);     // local rows of this lane
    const int r1 = r0 + 8;
    const float mu0 = g_mu[base_pix + r0], rs0 = g_rs[base_pix + r0];
    const float mu1 = g_mu[base_pix + r1], rs1 = g_rs[base_pix + r1];
    const float* xr0 = x + (size_t)(m0 + r0) * DIM;
    const float* xr1 = x + (size_t)(m0 + r1) * DIM;
    const unsigned* bfh = g_bdn_hi + which * (48 * 12 * 64) + lane * 2;
    const unsigned* bfl = g_bdn_lo + which * (48 * 12 * 64) + lane * 2;

    float acc[12][4] = {};
    const int c0o = (lane & 3) * 2;

    for (int k16 = 0; k16 < 48; k16++) {
        const int c0 = k16 * 16 + c0o;
        float2 x00 = *(const float2*)(xr0 + c0);
        float2 x10 = *(const float2*)(xr1 + c0);
        float2 x01 = *(const float2*)(xr0 + c0 + 8);
        float2 x11 = *(const float2*)(xr1 + c0 + 8);
        float2 w0 = *(const float2*)(lnw + c0);
        float2 w1 = *(const float2*)(lnw + c0 + 8);
        float2 v0 = *(const float2*)(lnb + c0);
        float2 v1 = *(const float2*)(lnb + c0 + 8);
        unsigned ah[4], al[4];
        ah[0] = pack_split((x00.x - mu0) * rs0 * w0.x + v0.x,
                           (x00.y - mu0) * rs0 * w0.y + v0.y, al[0]);
        ah[1] = pack_split((x10.x - mu1) * rs1 * w0.x + v0.x,
                           (x10.y - mu1) * rs1 * w0.y + v0.y, al[1]);
        ah[2] = pack_split((x01.x - mu0) * rs0 * w1.x + v1.x,
                           (x01.y - mu0) * rs0 * w1.y + v1.y, al[2]);
        ah[3] = pack_split((x11.x - mu1) * rs1 * w1.x + v1.x,
                           (x11.y - mu1) * rs1 * w1.y + v1.y, al[3]);

        const unsigned* fh = bfh + k16 * 12 * 64;
        const unsigned* fl = bfl + k16 * 12 * 64;
        #pragma unroll
        for (int nt8 = 0; nt8 < 12; nt8++) {
            uint2 bhv = *(const uint2*)(fh + nt8 * 64);
            uint2 blv = *(const uint2*)(fl + nt8 * 64);
            unsigned bh[2] = { bhv.x, bhv.y };
            unsigned bl[2] = { blv.x, blv.y };
            mma16816(acc[nt8], ah, bh);
            mma16816(acc[nt8], ah, bl);
            mma16816(acc[nt8], al, bh);
        }
    }

    // epilogue: NCHW stores (+bias). c0=(m,n) c1=(m,n+1) c2=(m+8,n) c3=(m+8,n+1)
    float* outp = which ? g_temb : g_xemb;
    const int mlo = wid * 16 + (lane >> 2);
    #pragma unroll
    for (int nt8 = 0; nt8 < 12; nt8++) {
        int n = nt8 * 8 + (lane & 3) * 2;
        float b0 = wb[n], b1 = wb[n + 1];
        size_t p0 = ((size_t)(b * MID + n)) * HWSZ + hw0;
        size_t p1 = ((size_t)(b * MID + n + 1)) * HWSZ + hw0;
        outp[p0 + mlo]     = acc[nt8][0] + b0;
        outp[p1 + mlo]     = acc[nt8][1] + b1;
        outp[p0 + mlo + 8] = acc[nt8][2] + b0;
        outp[p1 + mlo + 8] = acc[nt8][3] + b1;
    }
}

// ---------------------------------------------------------------------------
// up: Linear(96->768) + bias + residual. A staged via smem once (transpose),
// B direct fragment loads. ONE sync pair total, no per-tile barriers.
// smem 53248 B: [0 A_hi 26624][26624 A_lo 26624], pitch 52 words (208 B rows).
// ---------------------------------------------------------------------------
#define UP_SMEM 53248
#define UP_AHI  0
#define UP_ALO  26624
__global__ void __launch_bounds__(256, 2)
up_mma_kernel(const float* __restrict__ x,
              const float* __restrict__ upb,
              float* __restrict__ out)
{
    extern __shared__ __align__(16) char smem[];
    const uint32_t sb = smem_to_u32(smem);
    const int tid = threadIdx.x, wid = tid >> 5, lane = tid & 31;

    const int m0 = blockIdx.x * 128;
    const int b = m0 >> 12, hw0 = m0 & 4095;
    const float* fp = g_fds + (size_t)b * MID * HWSZ + hw0;

    unsigned* aH = (unsigned*)(smem + UP_AHI);
    unsigned* aL = (unsigned*)(smem + UP_ALO);

    // A: 128 pixels x 96 channels (transpose from NCHW), split bf16. word = m*52 + c2
    #pragma unroll
    for (int i = 0; i < 24; i++) {
        int e = tid + i * 256;
        int m = e & 127, c2 = e >> 7, c = c2 * 2;      // c2 in 0..47
        float v0 = fp[(size_t)c * HWSZ + m];
        float v1 = fp[(size_t)(c + 1) * HWSZ + m];
        unsigned lo, hi = pack_split(v0, v1, lo);
        aH[m * 52 + c2] = hi;
        aL[m * 52 + c2] = lo;
    }
    __syncthreads();

    const int m0w = wid * 16;
    const int mlo = m0w + (lane >> 2);

    for (int nt = 0; nt < 6; nt++) {
        float acc[16][4] = {};
        #pragma unroll
        for (int k16 = 0; k16 < 6; k16++) {
            unsigned ah[4], al[4];
            uint32_t arow = (uint32_t)((m0w + (lane & 15)) * 208 + k16 * 32 + (lane >> 4) * 16);
            ldsm_x4(ah, sb + UP_AHI + arow);
            ldsm_x4(al, sb + UP_ALO + arow);
            const unsigned* fh = g_bup_hi + (k16 * 96 + nt * 16) * 64 + lane * 2;
            const unsigned* fl = g_bup_lo + (k16 * 96 + nt * 16) * 64 + lane * 2;
            #pragma unroll
            for (int nt8 = 0; nt8 < 16; nt8++) {
                uint2 bhv = *(const uint2*)(fh + nt8 * 64);
                uint2 blv = *(const uint2*)(fl + nt8 * 64);
                unsigned bh[2] = { bhv.x, bhv.y };
                unsigned bl[2] = { blv.x, blv.y };
                mma16816(acc[nt8], ah, bh);
                mma16816(acc[nt8], ah, bl);
                mma16816(acc[nt8], al, bh);
            }
        }

        // epilogue: bias + residual, float2 per lane per row
        #pragma unroll
        for (int nt8 = 0; nt8 < 16; nt8++) {
            int n = nt * 128 + nt8 * 8 + (lane & 3) * 2;
            float b0 = upb[n], b1 = upb[n + 1];
            size_t base0 = (size_t)(m0 + mlo) * DIM + n;
            size_t base1 = (size_t)(m0 + mlo + 8) * DIM + n;
            float2 x0 = *(const float2*)&x[base0];
            float2 x1 = *(const float2*)&x[base1];
            float2 o0, o1;
            o0.x = acc[nt8][0] + b0 + x0.x;
            o0.y = acc[nt8][1] + b1 + x0.y;
            o1.x = acc[nt8][2] + b0 + x1.x;
            o1.y = acc[nt8][3] + b1 + x1.y;
            *(float2*)&out[base0] = o0;
            *(float2*)&out[base1] = o1;
        }
    }
}

// ---------------------------------------------------------------------------
// gvec = mean over H*W of g_xemb plane. grid = B*MID.
// ---------------------------------------------------------------------------
__global__ void gvec_kernel()
{
    __shared__ float red[256];
    const int bc = blockIdx.x;
    const float* p = g_xemb + (size_t)bc * HWSZ;
    float s = 0.f;
    for (int i = threadIdx.x; i < HWSZ; i += 256) s += p[i];
    red[threadIdx.x] = s;
    __syncthreads();
    for (int o = 128; o; o >>= 1) {
        if (threadIdx.x < o) red[threadIdx.x] += red[threadIdx.x + o];
        __syncthreads();
    }
    if (threadIdx.x == 0) g_gvec[bc] = red[0] * (1.f / HWSZ);
}

// ---------------------------------------------------------------------------
// per-batch MLP + softmax + dynamic kernel synthesis. grid = B.
// ---------------------------------------------------------------------------
__global__ void mlp_dyn_kernel(const float* __restrict__ m1w,
                               const float* __restrict__ m1b,
                               const float* __restrict__ m2w,
                               const float* __restrict__ m2b,
                               const float* __restrict__ basis)
{
    __shared__ float gv[MID];
    __shared__ float hid[24];
    __shared__ float wk[4];
    const int b = blockIdx.x, tid = threadIdx.x;

    if (tid < MID) gv[tid] = g_gvec[b * MID + tid];
    __syncthreads();
    if (tid < 24) {
        float s = m1b[tid];
        for (int c = 0; c < MID; c++) s += gv[c] * m1w[tid * MID + c];
        hid[tid] = fmaxf(s, 0.f);
    }
    __syncthreads();
    if (tid == 0) {
        float l[4];
        for (int k = 0; k < 4; k++) {
            float s = m2b[k];
            for (int j = 0; j < 24; j++) s += hid[j] * m2w[k * 24 + j];
            l[k] = s;
        }
        float mx = fmaxf(fmaxf(l[0], l[1]), fmaxf(l[2], l[3]));
        float e0 = expf(l[0] - mx), e1 = expf(l[1] - mx);
        float e2 = expf(l[2] - mx), e3 = expf(l[3] - mx);
        float inv = 1.f / (e0 + e1 + e2 + e3);
        wk[0] = e0 * inv; wk[1] = e1 * inv; wk[2] = e2 * inv; wk[3] = e3 * inv;
    }
    __syncthreads();
    const int n = MID * KSZ * KSZ;
    for (int e = tid; e < n; e += 128) {
        float s = 0.f;
        #pragma unroll
        for (int k = 0; k < 4; k++) s += wk[k] * basis[k * n + e];
        g_dyn[b * n + e] = s;
    }
}

// ---------------------------------------------------------------------------
// depthwise 3x3 + SiLU + 1x1 (96->192) -> gamma/beta -> common.
// ---------------------------------------------------------------------------
__global__ void head_common_kernel(const float* __restrict__ dww,
                                   const float* __restrict__ dwb,
                                   const float* __restrict__ pww,
                                   const float* __restrict__ pwb)
{
    __shared__ float y_s[MID * WW];
    const int b = blockIdx.x >> 6;
    const int h = blockIdx.x & 63;
    const float* tp = g_temb + (size_t)b * MID * HWSZ;

    for (int e = threadIdx.x; e < MID * WW; e += 256) {
        int c = e >> 6, wc = e & 63;
        const float* kw = dww + c * 9;
        float acc = 0.f;
        #pragma unroll
        for (int di = 0; di < 3; di++) {
            int hh = h + di - 1;
            if ((unsigned)hh < 64u) {
                const float* rowp = tp + (size_t)c * HWSZ + hh * 64;
                #pragma unroll
                for (int dj = 0; dj < 3; dj++) {
                    int wp = wc + dj - 1;
                    if ((unsigned)wp < 64u) acc += rowp[wp] * kw[di * 3 + dj];
                }
            }
        }
        float z = acc + dwb[c];
        y_s[c * 64 + wc] = z * (1.f / (1.f + expf(-z)));
    }
    __syncthreads();

    const float* xp = g_xemb + (size_t)b * MID * HWSZ + h * 64;
    float* cp = g_common + (size_t)b * MID * HWSZ + h * 64;
    for (int e = threadIdx.x; e < MID * WW; e += 256) {
        int c = e >> 6, wc = e & 63;
        float ga = pwb[c];
        float be = pwb[MID + c];
        const float* wg  = pww + (size_t)c * MID;
        const float* wbt = pww + (size_t)(MID + c) * MID;
        for (int cc = 0; cc < MID; cc++) {
            float yv = y_s[cc * 64 + wc];
            ga += yv * wg[cc];
            be += yv * wbt[cc];
        }
        float xe = xp[(size_t)c * HWSZ + wc];
        cp[(size_t)c * HWSZ + wc] = xe * (1.f + ga) + be;
    }
}

// ---------------------------------------------------------------------------
// FDS: circular 7x7 correlation (== rfft2/irfft2 of padded+rolled kernel).
// ---------------------------------------------------------------------------
__global__ void fds_kernel()
{
    __shared__ float pl[HWSZ];
    __shared__ float dd[KSZ * KSZ];
    const int bc = blockIdx.x;
    const float* src = g_common + (size_t)bc * HWSZ;
    for (int i = threadIdx.x; i < HWSZ; i += 256) pl[i] = src[i];
    if (threadIdx.x < KSZ * KSZ) dd[threadIdx.x] = g_dyn[bc * KSZ * KSZ + threadIdx.x];
    __syncthreads();

    float* dst = g_fds + (size_t)bc * HWSZ;
    for (int p = threadIdx.x; p < HWSZ; p += 256) {
        int yy = p >> 6, xx = p & 63;
        float acc = 0.f;
        #pragma unroll
        for (int i = 0; i < KSZ; i++) {
            const float* rowp = pl + (((yy + 3 - i) & 63) << 6);
            #pragma unroll
            for (int j = 0; j < KSZ; j++)
                acc += dd[i * KSZ + j] * rowp[(xx + 3 - j) & 63];
        }
        dst[p] = acc;
    }
}

// ---------------------------------------------------------------------------
extern "C" void kernel_launch(void* const* d_in, const int* in_sizes, int n_in,
                              void* d_out, int out_size)
{
    const float* x      = (const float*)d_in[0];
    const float* t      = (const float*)d_in[1];
    const float* ln_w   = (const float*)d_in[2];
    const float* ln_b   = (const float*)d_in[3];
    const float* down_w = (const float*)d_in[4];
    const float* down_b = (const float*)d_in[5];
    const float* ln1_w  = (const float*)d_in[6];
    const float* ln1_b  = (const float*)d_in[7];
    const float* down1_w= (const float*)d_in[8];
    const float* down1_b= (const float*)d_in[9];
    const float* dw_w   = (const float*)d_in[10];
    const float* dw_b   = (const float*)d_in[11];
    const float* pw_w   = (const float*)d_in[12];
    const float* pw_b   = (const float*)d_in[13];
    const float* mlp1_w = (const float*)d_in[14];
    const float* mlp1_b = (const float*)d_in[15];
    const float* mlp2_w = (const float*)d_in[16];
    const float* mlp2_b = (const float*)d_in[17];
    const float* basis  = (const float*)d_in[18];
    const float* up_w   = (const float*)d_in[19];
    const float* up_b   = (const float*)d_in[20];
    float* out = (float*)d_out;

    cudaFuncSetAttribute(up_mma_kernel,
                         cudaFuncAttributeMaxDynamicSharedMemorySize, UP_SMEM);

    stats_kernel<<<8192, 256>>>(x, t);
    prep_down_kernel<<<288, 256>>>(down_w, down1_w);
    prep_up_kernel<<<144, 256>>>(up_w);
    ln_down_mma_kernel<<<256, 256>>>(x, ln_w,  ln_b,  down_b,  0);
    ln_down_mma_kernel<<<256, 256>>>(t, ln1_w, ln1_b, down1_b, 1);
    gvec_kernel<<<BB * MID, 256>>>();
    mlp_dyn_kernel<<<BB, 128>>>(mlp1_w, mlp1_b, mlp2_w, mlp2_b, basis);
    head_common_kernel<<<BB * HH, 256>>>(dw_w, dw_b, pw_w, pw_b);
    fds_kernel<<<BB * MID, 256>>>();
    up_mma_kernel<<<256, 256, UP_SMEM>>>(x, up_b, out);
}

// round 13
// speedup vs baseline: 1.7753x; 1.0150x over previous
#include <cuda_runtime.h>
#include <cuda_bf16.h>
#include <cstdint>
#include <math.h>

#define BB   8
#define HH   64
#define WW   64
#define DIM  768
#define MID  96
#define HWSZ 4096
#define KSZ  7

// ====================== warp-MMA helpers (sm_80+ portable) ==================
__device__ __forceinline__ uint32_t smem_to_u32(const void* p) {
    uint32_t a;
    asm("{ .reg .u64 t; cvta.to.shared.u64 t, %1; cvt.u32.u64 %0, t; }"
        : "=r"(a) : "l"(p));
    return a;
}
__device__ __forceinline__ void ldsm_x4(unsigned* r, uint32_t addr) {
    asm volatile("ldmatrix.sync.aligned.m8n8.x4.shared.b16 {%0,%1,%2,%3}, [%4];"
        : "=r"(r[0]), "=r"(r[1]), "=r"(r[2]), "=r"(r[3]) : "r"(addr));
}
__device__ __forceinline__ void mma16816(float* c, const unsigned* a, const unsigned* b) {
    asm volatile("mma.sync.aligned.m16n8k16.row.col.f32.bf16.bf16.f32 "
        "{%0,%1,%2,%3}, {%4,%5,%6,%7}, {%8,%9}, {%0,%1,%2,%3};"
        : "+f"(c[0]), "+f"(c[1]), "+f"(c[2]), "+f"(c[3])
        : "r"(a[0]), "r"(a[1]), "r"(a[2]), "r"(a[3]), "r"(b[0]), "r"(b[1]));
}

// split fp32 pair -> bf16x2 hi word (ret, y1 in upper half) + bf16x2 lo word.
// cvt.rn.bf16x2.f32 packs both halves in ONE instruction; residual uses the
// exact identity float(bf16) == bits<<16. Numerically identical to the
// two-step __float2bfloat16_rn version.
__device__ __forceinline__ unsigned pack_split(float y0, float y1, unsigned& lo_out) {
    unsigned hi;
    asm("cvt.rn.bf16x2.f32 %0, %1, %2;" : "=r"(hi) : "f"(y1), "f"(y0));
    float h0 = __uint_as_float(hi << 16);
    float h1 = __uint_as_float(hi & 0xffff0000u);
    float r0 = y0 - h0;
    float r1 = y1 - h1;
    asm("cvt.rn.bf16x2.f32 %0, %1, %2;" : "=r"(lo_out) : "f"(r1), "f"(r0));
    return hi;
}

// ============================ scratch =======================================
__device__ float g_xemb[BB * MID * HWSZ];
__device__ float g_temb[BB * MID * HWSZ];
__device__ float g_common[BB * MID * HWSZ];
__device__ float g_fds[BB * MID * HWSZ];
__device__ float g_gvec[BB * MID];
__device__ float g_dyn[BB * MID * KSZ * KSZ];
__device__ float g_mu[2 * BB * HWSZ];
__device__ float g_rs[2 * BB * HWSZ];
// pre-split weights, PAIR-interleaved fragment order:
// down: [which][k16 0..47][pair 0..5][lane 0..31][w 0..3]
//   w0,w1 = nt8=2p words; w2,w3 = nt8=2p+1 words
__device__ __align__(16) unsigned g_bdn_hi[2 * 48 * 6 * 32 * 4];
__device__ __align__(16) unsigned g_bdn_lo[2 * 48 * 6 * 32 * 4];
// up: [k16 0..5][ptot 0..47][lane][w 0..3]   (ptot = nt*8 + p)
__device__ __align__(16) unsigned g_bup_hi[6 * 48 * 32 * 4];
__device__ __align__(16) unsigned g_bup_lo[6 * 48 * 32 * 4];

// ---------------------------------------------------------------------------
// LN stats pre-pass (+ zero g_gvec from block 0).
// ---------------------------------------------------------------------------
__global__ void stats_kernel(const float* __restrict__ x, const float* __restrict__ t)
{
    if (blockIdx.x == 0) {
        for (int i = threadIdx.x; i < BB * MID; i += 256) g_gvec[i] = 0.f;
    }
    const int wid = threadIdx.x >> 5, lane = threadIdx.x & 31;
    const int pix = blockIdx.x * 8 + wid;                 // 0 .. 65535
    const float* src = (pix >= BB * HWSZ) ? t : x;
    const int p = pix & (BB * HWSZ - 1);
    const float4* row = (const float4*)(src + (size_t)p * DIM);
    float s = 0.f, s2 = 0.f;
    #pragma unroll
    for (int j = 0; j < 6; j++) {
        float4 v = row[lane + 32 * j];
        s  += v.x + v.y + v.z + v.w;
        s2 += v.x * v.x + v.y * v.y + v.z * v.z + v.w * v.w;
    }
    #pragma unroll
    for (int o = 16; o; o >>= 1) {
        s  += __shfl_xor_sync(0xffffffffu, s,  o);
        s2 += __shfl_xor_sync(0xffffffffu, s2, o);
    }
    if (lane == 0) {
        float mu  = s * (1.f / DIM);
        float var = s2 * (1.f / DIM) - mu * mu;
        g_mu[pix] = mu;
        g_rs[pix] = rsqrtf(var + 1e-6f);
    }
}

// ---------------------------------------------------------------------------
// Weight prep -> pair-interleaved fragment-order split-bf16 layouts.
// ---------------------------------------------------------------------------
__global__ void prep_down_kernel(const float* __restrict__ w0, const float* __restrict__ w1)
{
    int e = blockIdx.x * 256 + threadIdx.x;               // < 73728
    if (e >= 2 * 48 * 6 * 32 * 4) return;
    int w    = e & 3;
    int t    = e >> 2;
    int lane = t & 31;  t >>= 5;
    int p    = t % 6;   t /= 6;
    int k16  = t % 48;
    int which = t / 48;
    const float* wp = which ? w1 : w0;
    int n = p * 16 + ((w >> 1) ? 8 : 0) + (lane >> 2);
    int k = k16 * 16 + (lane & 3) * 2 + (w & 1) * 8;
    float v0 = wp[(size_t)n * DIM + k];
    float v1 = wp[(size_t)n * DIM + k + 1];
    unsigned lo, hi = pack_split(v0, v1, lo);
    g_bdn_hi[e] = hi;
    g_bdn_lo[e] = lo;
}

__global__ void prep_up_kernel(const float* __restrict__ upw)
{
    int e = blockIdx.x * 256 + threadIdx.x;               // < 36864
    if (e >= 6 * 48 * 32 * 4) return;
    int w    = e & 3;
    int t    = e >> 2;
    int lane = t & 31;  t >>= 5;
    int ptot = t % 48;
    int k16  = t / 48;
    int n = ptot * 16 + ((w >> 1) ? 8 : 0) + (lane >> 2);
    int k = k16 * 16 + (lane & 3) * 2 + (w & 1) * 8;
    float v0 = upw[(size_t)n * MID + k];
    float v1 = upw[(size_t)n * MID + k + 1];
    unsigned lo, hi = pack_split(v0, v1, lo);
    g_bup_hi[e] = hi;
    g_bup_lo[e] = lo;
}

// ---------------------------------------------------------------------------
// Fused LN + Linear(768->96), register-resident mma.sync. No smem, no barriers.
// 128 pixels/CTA (8 warps x 16 rows), N=96, K=768 (48 k16 steps).
// which==0 additionally accumulates g_gvec partial sums via atomics.
// ---------------------------------------------------------------------------
__global__ void __launch_bounds__(256, 2)
ln_down_mma_kernel(const float* __restrict__ x,
                   const float* __restrict__ lnw,
                   const float* __restrict__ lnb,
                   const float* __restrict__ wb,
                   int which)
{
    const int tid = threadIdx.x, wid = tid >> 5, lane = tid & 31;
    const int m0 = blockIdx.x * 128;
    const int b = m0 >> 12, hw0 = m0 & 4095;
    const int base_pix = which * (BB * HWSZ) + m0;

    const int r0 = wid * 16 + (lane >> 2);     // local rows of this lane
    const int r1 = r0 + 8;
    const float mu0 = g_mu[base_pix + r0], rs0 = g_rs[base_pix + r0];
    const float mu1 = g_mu[base_pix + r1], rs1 = g_rs[base_pix + r1];
    const float* xr0 = x + (size_t)(m0 + r0) * DIM;
    const float* xr1 = x + (size_t)(m0 + r1) * DIM;
    const unsigned* bfh = g_bdn_hi + which * (48 * 768) + lane * 4;
    const unsigned* bfl = g_bdn_lo + which * (48 * 768) + lane * 4;

    float acc[12][4] = {};
    const int c0o = (lane & 3) * 2;

    for (int k16 = 0; k16 < 48; k16++) {
        const int c0 = k16 * 16 + c0o;
        float2 x00 = *(const float2*)(xr0 + c0);
        float2 x10 = *(const float2*)(xr1 + c0);
        float2 x01 = *(const float2*)(xr0 + c0 + 8);
        float2 x11 = *(const float2*)(xr1 + c0 + 8);
        float2 w0 = *(const float2*)(lnw + c0);
        float2 w1 = *(const float2*)(lnw + c0 + 8);
        float2 v0 = *(const float2*)(lnb + c0);
        float2 v1 = *(const float2*)(lnb + c0 + 8);
        unsigned ah[4], al[4];
        ah[0] = pack_split((x00.x - mu0) * rs0 * w0.x + v0.x,
                           (x00.y - mu0) * rs0 * w0.y + v0.y, al[0]);
        ah[1] = pack_split((x10.x - mu1) * rs1 * w0.x + v0.x,
                           (x10.y - mu1) * rs1 * w0.y + v0.y, al[1]);
        ah[2] = pack_split((x01.x - mu0) * rs0 * w1.x + v1.x,
                           (x01.y - mu0) * rs0 * w1.y + v1.y, al[2]);
        ah[3] = pack_split((x11.x - mu1) * rs1 * w1.x + v1.x,
                           (x11.y - mu1) * rs1 * w1.y + v1.y, al[3]);

        const unsigned* fh = bfh + k16 * 768;
        const unsigned* fl = bfl + k16 * 768;
        #pragma unroll
        for (int p = 0; p < 6; p++) {
            uint4 hv = *(const uint4*)(fh + p * 128);
            uint4 lv = *(const uint4*)(fl + p * 128);
            unsigned bhE[2] = { hv.x, hv.y };
            unsigned bhO[2] = { hv.z, hv.w };
            unsigned blE[2] = { lv.x, lv.y };
            unsigned blO[2] = { lv.z, lv.w };
            mma16816(acc[2 * p],     ah, bhE);
            mma16816(acc[2 * p],     ah, blE);
            mma16816(acc[2 * p],     al, bhE);
            mma16816(acc[2 * p + 1], ah, bhO);
            mma16816(acc[2 * p + 1], ah, blO);
            mma16816(acc[2 * p + 1], al, bhO);
        }
    }

    // epilogue: NCHW stores (+bias). c0=(m,n) c1=(m,n+1) c2=(m+8,n) c3=(m+8,n+1)
    float* outp = which ? g_temb : g_xemb;
    const int mlo = wid * 16 + (lane >> 2);
    #pragma unroll
    for (int nt8 = 0; nt8 < 12; nt8++) {
        int n = nt8 * 8 + (lane & 3) * 2;
        float b0 = wb[n], b1 = wb[n + 1];
        float o0 = acc[nt8][0] + b0;
        float o1 = acc[nt8][1] + b1;
        float o2 = acc[nt8][2] + b0;
        float o3 = acc[nt8][3] + b1;
        size_t p0 = ((size_t)(b * MID + n)) * HWSZ + hw0;
        size_t p1 = ((size_t)(b * MID + n + 1)) * HWSZ + hw0;
        outp[p0 + mlo]     = o0;
        outp[p1 + mlo]     = o1;
        outp[p0 + mlo + 8] = o2;
        outp[p1 + mlo + 8] = o3;
        if (which == 0) {
            // partial sums for gvec: reduce over this warp's 16 rows
            float s0 = o0 + o2;
            float s1 = o1 + o3;
            #pragma unroll
            for (int o = 4; o < 32; o <<= 1) {
                s0 += __shfl_xor_sync(0xffffffffu, s0, o);
                s1 += __shfl_xor_sync(0xffffffffu, s1, o);
            }
            if (lane < 4) {
                atomicAdd(&g_gvec[b * MID + n], s0);
                atomicAdd(&g_gvec[b * MID + n + 1], s1);
            }
        }
    }
}

// ---------------------------------------------------------------------------
// up: Linear(96->768) + bias + residual. A staged via smem once (transpose),
// B direct pair-fragment loads. ONE sync pair total.
// smem 53248 B: [0 A_hi 26624][26624 A_lo 26624], pitch 52 words (208 B rows).
// ---------------------------------------------------------------------------
#define UP_SMEM 53248
#define UP_AHI  0
#define UP_ALO  26624
__global__ void __launch_bounds__(256, 2)
up_mma_kernel(const float* __restrict__ x,
              const float* __restrict__ upb,
              float* __restrict__ out)
{
    extern __shared__ __align__(16) char smem[];
    const uint32_t sb = smem_to_u32(smem);
    const int tid = threadIdx.x, wid = tid >> 5, lane = tid & 31;

    const int m0 = blockIdx.x * 128;
    const int b = m0 >> 12, hw0 = m0 & 4095;
    const float* fp = g_fds + (size_t)b * MID * HWSZ + hw0;

    unsigned* aH = (unsigned*)(smem + UP_AHI);
    unsigned* aL = (unsigned*)(smem + UP_ALO);

    // A: 128 pixels x 96 channels (transpose from NCHW), split bf16. word = m*52 + c2
    #pragma unroll
    for (int i = 0; i < 24; i++) {
        int e = tid + i * 256;
        int m = e & 127, c2 = e >> 7, c = c2 * 2;      // c2 in 0..47
        float v0 = fp[(size_t)c * HWSZ + m];
        float v1 = fp[(size_t)(c + 1) * HWSZ + m];
        unsigned lo, hi = pack_split(v0, v1, lo);
        aH[m * 52 + c2] = hi;
        aL[m * 52 + c2] = lo;
    }
    __syncthreads();

    const int m0w = wid * 16;
    const int mlo = m0w + (lane >> 2);

    for (int nt = 0; nt < 6; nt++) {
        float acc[16][4] = {};
        #pragma unroll
        for (int k16 = 0; k16 < 6; k16++) {
            unsigned ah[4], al[4];
            uint32_t arow = (uint32_t)((m0w + (lane & 15)) * 208 + k16 * 32 + (lane >> 4) * 16);
            ldsm_x4(ah, sb + UP_AHI + arow);
            ldsm_x4(al, sb + UP_ALO + arow);
            const unsigned* fh = g_bup_hi + (k16 * 48 + nt * 8) * 128 + lane * 4;
            const unsigned* fl = g_bup_lo + (k16 * 48 + nt * 8) * 128 + lane * 4;
            #pragma unroll
            for (int p = 0; p < 8; p++) {
                uint4 hv = *(const uint4*)(fh + p * 128);
                uint4 lv = *(const uint4*)(fl + p * 128);
                unsigned bhE[2] = { hv.x, hv.y };
                unsigned bhO[2] = { hv.z, hv.w };
                unsigned blE[2] = { lv.x, lv.y };
                unsigned blO[2] = { lv.z, lv.w };
                mma16816(acc[2 * p],     ah, bhE);
                mma16816(acc[2 * p],     ah, blE);
                mma16816(acc[2 * p],     al, bhE);
                mma16816(acc[2 * p + 1], ah, bhO);
                mma16816(acc[2 * p + 1], ah, blO);
                mma16816(acc[2 * p + 1], al, bhO);
            }
        }

        // epilogue: bias + residual, float2 per lane per row
        #pragma unroll
        for (int nt8 = 0; nt8 < 16; nt8++) {
            int n = nt * 128 + nt8 * 8 + (lane & 3) * 2;
            float b0 = upb[n], b1 = upb[n + 1];
            size_t base0 = (size_t)(m0 + mlo) * DIM + n;
            size_t base1 = (size_t)(m0 + mlo + 8) * DIM + n;
            float2 x0 = *(const float2*)&x[base0];
            float2 x1 = *(const float2*)&x[base1];
            float2 o0, o1;
            o0.x = acc[nt8][0] + b0 + x0.x;
            o0.y = acc[nt8][1] + b1 + x0.y;
            o1.x = acc[nt8][2] + b0 + x1.x;
            o1.y = acc[nt8][3] + b1 + x1.y;
            *(float2*)&out[base0] = o0;
            *(float2*)&out[base1] = o1;
        }
    }
}

// ---------------------------------------------------------------------------
// per-batch MLP + softmax + dynamic kernel synthesis. grid = B.
// g_gvec holds SUMS (from ln_down atomics); divide by HWSZ here.
// ---------------------------------------------------------------------------
__global__ void mlp_dyn_kernel(const float* __restrict__ m1w,
                               const float* __restrict__ m1b,
                               const float* __restrict__ m2w,
                               const float* __restrict__ m2b,
                               const float* __restrict__ basis)
{
    __shared__ float gv[MID];
    __shared__ float hid[24];
    __shared__ float wk[4];
    const int b = blockIdx.x, tid = threadIdx.x;

    if (tid < MID) gv[tid] = g_gvec[b * MID + tid] * (1.f / HWSZ);
    __syncthreads();
    if (tid < 24) {
        float s = m1b[tid];
        for (int c = 0; c < MID; c++) s += gv[c] * m1w[tid * MID + c];
        hid[tid] = fmaxf(s, 0.f);
    }
    __syncthreads();
    if (tid == 0) {
        float l[4];
        for (int k = 0; k < 4; k++) {
            float s = m2b[k];
            for (int j = 0; j < 24; j++) s += hid[j] * m2w[k * 24 + j];
            l[k] = s;
        }
        float mx = fmaxf(fmaxf(l[0], l[1]), fmaxf(l[2], l[3]));
        float e0 = expf(l[0] - mx), e1 = expf(l[1] - mx);
        float e2 = expf(l[2] - mx), e3 = expf(l[3] - mx);
        float inv = 1.f / (e0 + e1 + e2 + e3);
        wk[0] = e0 * inv; wk[1] = e1 * inv; wk[2] = e2 * inv; wk[3] = e3 * inv;
    }
    __syncthreads();
    const int n = MID * KSZ * KSZ;
    for (int e = tid; e < n; e += 128) {
        float s = 0.f;
        #pragma unroll
        for (int k = 0; k < 4; k++) s += wk[k] * basis[k * n + e];
        g_dyn[b * n + e] = s;
    }
}

// ---------------------------------------------------------------------------
// depthwise 3x3 + SiLU + 1x1 (96->192) -> gamma/beta -> common.
// ---------------------------------------------------------------------------
__global__ void head_common_kernel(const float* __restrict__ dww,
                                   const float* __restrict__ dwb,
                                   const float* __restrict__ pww,
                                   const float* __restrict__ pwb)
{
    __shared__ float y_s[MID * WW];
    const int b = blockIdx.x >> 6;
    const int h = blockIdx.x & 63;
    const float* tp = g_temb + (size_t)b * MID * HWSZ;

    for (int e = threadIdx.x; e < MID * WW; e += 256) {
        int c = e >> 6, wc = e & 63;
        const float* kw = dww + c * 9;
        float acc = 0.f;
        #pragma unroll
        for (int di = 0; di < 3; di++) {
            int hh = h + di - 1;
            if ((unsigned)hh < 64u) {
                const float* rowp = tp + (size_t)c * HWSZ + hh * 64;
                #pragma unroll
                for (int dj = 0; dj < 3; dj++) {
                    int wp = wc + dj - 1;
                    if ((unsigned)wp < 64u) acc += rowp[wp] * kw[di * 3 + dj];
                }
            }
        }
        float z = acc + dwb[c];
        y_s[c * 64 + wc] = z * (1.f / (1.f + expf(-z)));
    }
    __syncthreads();

    const float* xp = g_xemb + (size_t)b * MID * HWSZ + h * 64;
    float* cp = g_common + (size_t)b * MID * HWSZ + h * 64;
    for (int e = threadIdx.x; e < MID * WW; e += 256) {
        int c = e >> 6, wc = e & 63;
        float ga = pwb[c];
        float be = pwb[MID + c];
        const float* wg  = pww + (size_t)c * MID;
        const float* wbt = pww + (size_t)(MID + c) * MID;
        for (int cc = 0; cc < MID; cc++) {
            float yv = y_s[cc * 64 + wc];
            ga += yv * wg[cc];
            be += yv * wbt[cc];
        }
        float xe = xp[(size_t)c * HWSZ + wc];
        cp[(size_t)c * HWSZ + wc] = xe * (1.f + ga) + be;
    }
}

// ---------------------------------------------------------------------------
// FDS: circular 7x7 correlation (== rfft2/irfft2 of padded+rolled kernel).
// ---------------------------------------------------------------------------
__global__ void fds_kernel()
{
    __shared__ float pl[HWSZ];
    __shared__ float dd[KSZ * KSZ];
    const int bc = blockIdx.x;
    const float* src = g_common + (size_t)bc * HWSZ;
    for (int i = threadIdx.x; i < HWSZ; i += 256) pl[i] = src[i];
    if (threadIdx.x < KSZ * KSZ) dd[threadIdx.x] = g_dyn[bc * KSZ * KSZ + threadIdx.x];
    __syncthreads();

    float* dst = g_fds + (size_t)bc * HWSZ;
    for (int p = threadIdx.x; p < HWSZ; p += 256) {
        int yy = p >> 6, xx = p & 63;
        float acc = 0.f;
        #pragma unroll
        for (int i = 0; i < KSZ; i++) {
            const float* rowp = pl + (((yy + 3 - i) & 63) << 6);
            #pragma unroll
            for (int j = 0; j < KSZ; j++)
                acc += dd[i * KSZ + j] * rowp[(xx + 3 - j) & 63];
        }
        dst[p] = acc;
    }
}

// ---------------------------------------------------------------------------
extern "C" void kernel_launch(void* const* d_in, const int* in_sizes, int n_in,
                              void* d_out, int out_size)
{
    const float* x      = (const float*)d_in[0];
    const float* t      = (const float*)d_in[1];
    const float* ln_w   = (const float*)d_in[2];
    const float* ln_b   = (const float*)d_in[3];
    const float* down_w = (const float*)d_in[4];
    const float* down_b = (const float*)d_in[5];
    const float* ln1_w  = (const float*)d_in[6];
    const float* ln1_b  = (const float*)d_in[7];
    const float* down1_w= (const float*)d_in[8];
    const float* down1_b= (const float*)d_in[9];
    const float* dw_w   = (const float*)d_in[10];
    const float* dw_b   = (const float*)d_in[11];
    const float* pw_w   = (const float*)d_in[12];
    const float* pw_b   = (const float*)d_in[13];
    const float* mlp1_w = (const float*)d_in[14];
    const float* mlp1_b = (const float*)d_in[15];
    const float* mlp2_w = (const float*)d_in[16];
    const float* mlp2_b = (const float*)d_in[17];
    const float* basis  = (const float*)d_in[18];
    const float* up_w   = (const float*)d_in[19];
    const float* up_b   = (const float*)d_in[20];
    float* out = (float*)d_out;

    cudaFuncSetAttribute(up_mma_kernel,
                         cudaFuncAttributeMaxDynamicSharedMemorySize, UP_SMEM);

    stats_kernel<<<8192, 256>>>(x, t);
    prep_down_kernel<<<288, 256>>>(down_w, down1_w);
    prep_up_kernel<<<144, 256>>>(up_w);
    ln_down_mma_kernel<<<256, 256>>>(x, ln_w,  ln_b,  down_b,  0);
    ln_down_mma_kernel<<<256, 256>>>(t, ln1_w, ln1_b, down1_b, 1);
    mlp_dyn_kernel<<<BB, 128>>>(mlp1_w, mlp1_b, mlp2_w, mlp2_b, basis);
    head_common_kernel<<<BB * HH, 256>>>(dw_w, dw_b, pw_w, pw_b);
    fds_kernel<<<BB * MID, 256>>>();
    up_mma_kernel<<<256, 256, UP_SMEM>>>(x, up_b, out);
}